// round 10
// baseline (speedup 1.0000x reference)
#include <cuda_runtime.h>

// ---------------------------------------------------------------------------
// SSIM fused single-kernel. Tile 32x64 outputs/block, 384 threads, 3 CTAs/SM.
//   P1: stage interleaved AB plane (float2, zero-padded)
//   P2: horizontal 11-tap conv, packed f32x2 scatter -> packed H planes:
//       Hm=(mu1,mu2) float2, Hs=(E11,E22) float2, Hp=E12 scalar (transposed)
//   P3: vertical 11-tap conv: 2 packed f32x2 streams + 1 scalar + SSIM + reduce
// ---------------------------------------------------------------------------

typedef unsigned long long ull;

#define IMG      512
#define TW       32
#define TH       64
#define HALO     5
#define ROWS     74                // TH + 2*HALO
#define ABROW    46                // AB plane row stride in float2 units
#define ABPLANE  (ROWS * ABROW)    // 3404 float2
#define NTHREADS 384
#define NWARPS   12
#define NBLOCKS  (16 * 8 * 64)     // 8192

#define HPCOL    78                // packed H column stride (float2 units)
#define HPPLANE  (32 * HPCOL)      // 2496 float2 per packed plane
#define PPCOL    76                // pp column stride (floats)

// float offsets
#define HOFF     (2 * ABPLANE)                 // 6808: Hm base (as float2*)
#define HSOFF    (HOFF + 2 * HPPLANE)          // Hs base (floats)
#define PPOFF    (HSOFF + 2 * HPPLANE)         // pp base (floats)
#define SMEM_FLOATS (PPOFF + 32 * PPCOL + 16)  // +16 pad for pp tail over-read
#define SMEM_BYTES  (SMEM_FLOATS * (int)sizeof(float))   // 76,960 B

#define SSIM_C1 0.0001f
#define SSIM_C2 0.0009f

// 1-D Gaussian, sigma=1.5, 11 taps, normalized (literals -> FFMA-imm)
static __device__ __forceinline__ float gwk(int k) {
    const float g[11] = { 1.0283735e-03f, 7.5987582e-03f, 3.6000773e-02f,
                          1.0936068e-01f, 2.1300554e-01f, 2.6601174e-01f,
                          2.1300554e-01f, 1.0936068e-01f, 3.6000773e-02f,
                          7.5987582e-03f, 1.0283735e-03f };
    return g[k];   // k compile-time under full unroll -> immediate
}

#define CONV11(X, c)                                                          \
    fmaf(gwk(0), (X)[(c)+0], fmaf(gwk(1), (X)[(c)+1], fmaf(gwk(2), (X)[(c)+2],\
    fmaf(gwk(3), (X)[(c)+3], fmaf(gwk(4), (X)[(c)+4], fmaf(gwk(5), (X)[(c)+5],\
    fmaf(gwk(6), (X)[(c)+6], fmaf(gwk(7), (X)[(c)+7], fmaf(gwk(8), (X)[(c)+8],\
    fmaf(gwk(9), (X)[(c)+9], gwk(10) * (X)[(c)+10]))))))))))

// packed f32x2 helpers
__device__ __forceinline__ ull pk2(float lo, float hi) {
    ull d; asm("mov.b64 %0, {%1, %2};" : "=l"(d) : "f"(lo), "f"(hi)); return d;
}
__device__ __forceinline__ void unpk2(ull v, float& lo, float& hi) {
    asm("mov.b64 {%0, %1}, %2;" : "=f"(lo), "=f"(hi) : "l"(v));
}
__device__ __forceinline__ ull mul2(ull a, ull b) {
    ull d; asm("mul.rn.f32x2 %0, %1, %2;" : "=l"(d) : "l"(a), "l"(b)); return d;
}
__device__ __forceinline__ ull fma2(ull a, ull b, ull c) {
    ull d; asm("fma.rn.f32x2 %0, %1, %2, %3;" : "=l"(d) : "l"(a), "l"(b), "l"(c)); return d;
}
// packed symmetric 11-tap conv; W[0..5], c compile-time
__device__ __forceinline__ ull conv11p(const ull* y, int c, const ull* W) {
    ull a = mul2(W[0], y[c + 10]);
    a = fma2(W[1], y[c + 9], a);
    a = fma2(W[2], y[c + 8], a);
    a = fma2(W[3], y[c + 7], a);
    a = fma2(W[4], y[c + 6], a);
    a = fma2(W[5], y[c + 5], a);
    a = fma2(W[4], y[c + 4], a);
    a = fma2(W[3], y[c + 3], a);
    a = fma2(W[2], y[c + 2], a);
    a = fma2(W[1], y[c + 1], a);
    a = fma2(W[0], y[c + 0], a);
    return a;
}

static __device__ double   g_acc = 0.0;
static __device__ unsigned g_cnt = 0u;

__global__ __launch_bounds__(NTHREADS, 3)
void ssim_kernel(const float* __restrict__ img1, const float* __restrict__ img2,
                 float* __restrict__ out) {
    extern __shared__ float sm[];
    float2* sAB = reinterpret_cast<float2*>(sm);
    ull*    sHm = reinterpret_cast<ull*>(sm + HOFF);    // packed (mu1,mu2)
    ull*    sHs = reinterpret_cast<ull*>(sm + HSOFF);   // packed (E11,E22)
    float*  sPP = sm + PPOFF;                            // scalar E12
    __shared__ float red[NWARPS];

    const int t    = threadIdx.x;
    const int lane = t & 31;
    const int wid  = t >> 5;        // 0..11
    const int gx0  = blockIdx.x * TW - HALO;
    const int gy0  = blockIdx.y * TH - HALO;
    const float* base1 = img1 + (size_t)blockIdx.z * (IMG * IMG);
    const float* base2 = img2 + (size_t)blockIdx.z * (IMG * IMG);

    // ---- Phase 1: stage interleaved AB (zero-padded), warp per row ----
    for (int r = wid; r < ROWS; r += NWARPS) {
        const int gy = gy0 + r;
        const bool yok = (unsigned)gy < (unsigned)IMG;
        const float* r1 = base1 + gy * IMG;
        const float* r2 = base2 + gy * IMG;
#pragma unroll
        for (int seg = 0; seg < 2; seg++) {
            const int c = lane + seg * 32;
            if (seg == 1 && lane >= 10) break;
            const int gx = gx0 + c;
            const bool ok = yok && (unsigned)gx < (unsigned)IMG;
            sAB[r * ABROW + c] = make_float2(ok ? r1[gx] : 0.0f,
                                             ok ? r2[gx] : 0.0f);
        }
    }
    __syncthreads();

    // ---- Phase 2: horizontal conv, packed scatter, 2 halves of 4 outputs ----
    if (t < 4 * ROWS) {
        const int q = t / ROWS;          // 0..3
        const int r = t - q * ROWS;      // 0..73
        const int cbase = q * 8;
        const float2* abrow = sAB + r * ABROW;

        ull W2[6];
#pragma unroll
        for (int k = 0; k < 6; k++) W2[k] = pk2(gwk(k), gwk(k));

#pragma unroll
        for (int half = 0; half < 2; half++) {
            const int base = cbase + half * 4;   // first output col of half
            ull  mAB[4] = {0ull, 0ull, 0ull, 0ull};
            ull  sSQ[4] = {0ull, 0ull, 0ull, 0ull};
            float pp[4] = {0.f, 0.f, 0.f, 0.f};

            // stream 14 window elements as 7x LDS.128 (2 packed pairs each)
#pragma unroll
            for (int blk = 0; blk < 7; blk++) {
                const ulonglong2 v = *reinterpret_cast<const ulonglong2*>(
                    abrow + base + 2 * blk);
#pragma unroll
                for (int sub = 0; sub < 2; sub++) {
                    const int e = 2 * blk + sub;      // 0..13, compile-time
                    const ull ab = sub ? v.y : v.x;
                    float a, b;
                    unpk2(ab, a, b);
                    const ull   sq   = mul2(ab, ab);
                    const float prod = a * b;
#pragma unroll
                    for (int j = 0; j < 4; j++) {
                        const int k = e - j;          // compile-time
                        if (k >= 0 && k < 11) {
                            const int ks = (k < 6) ? k : 10 - k;
                            mAB[j] = fma2(W2[ks], ab, mAB[j]);
                            sSQ[j] = fma2(W2[ks], sq, sSQ[j]);
                            pp[j]  = fmaf(gwk(k), prod, pp[j]);
                        }
                    }
                }
            }

            // packed stores into transposed H planes
#pragma unroll
            for (int j = 0; j < 4; j++) {
                const int hc = base + j;
                sHm[hc * HPCOL + r] = mAB[j];   // ST.64, phase-conflict-free
                sHs[hc * HPCOL + r] = sSQ[j];
                sPP[hc * PPCOL + r] = pp[j];
            }
        }
    }
    __syncthreads();

    // ---- Phase 3: vertical conv (packed x2 + scalar) + SSIM + reduce ----
    {
        // warps 0..7: 6 rows from r0=6w ; warps 8..11: 4 rows from 48+4(w-8)
        const int six = (wid < 8);
        const int r0  = six ? 6 * wid : 48 + 4 * (wid - 8);
        const int cnt = six ? 6 : 4;
        const int rb  = r0 & ~3;        // aligned load base (d = r0-rb in {0,2})
        const int col = lane;

        ull W2[6];
#pragma unroll
        for (int k = 0; k < 6; k++) W2[k] = pk2(gwk(k), gwk(k));

        // packed mu conv: rows rb..rb+17 as 9x LDS.128 (fits in HPCOL=78)
        ull resM[6], resS[6];
        {
            ull y[18];
            const ulonglong2* p = reinterpret_cast<const ulonglong2*>(
                sHm + col * HPCOL + rb);
#pragma unroll
            for (int i = 0; i < 9; i++) {
                const ulonglong2 v = p[i];
                y[2 * i]     = v.x;
                y[2 * i + 1] = v.y;
            }
            if (r0 & 2) {
#pragma unroll
                for (int i = 0; i < 6; i++) resM[i] = conv11p(y, i + 2, W2);
            } else {
#pragma unroll
                for (int i = 0; i < 6; i++) resM[i] = conv11p(y, i, W2);
            }
        }
        {
            ull y[18];
            const ulonglong2* p = reinterpret_cast<const ulonglong2*>(
                sHs + col * HPCOL + rb);
#pragma unroll
            for (int i = 0; i < 9; i++) {
                const ulonglong2 v = p[i];
                y[2 * i]     = v.x;
                y[2 * i + 1] = v.y;
            }
            if (r0 & 2) {
#pragma unroll
                for (int i = 0; i < 6; i++) resS[i] = conv11p(y, i + 2, W2);
            } else {
#pragma unroll
                for (int i = 0; i < 6; i++) resS[i] = conv11p(y, i, W2);
            }
        }
        // scalar pp conv: rows rb..rb+19 as 5x LDS.128 (pad covers tail)
        float resP[6];
        {
            float y[20];
            const float* p = sPP + col * PPCOL + rb;
#pragma unroll
            for (int i = 0; i < 5; i++) {
                const float4 v = *reinterpret_cast<const float4*>(p + 4 * i);
                y[4*i+0] = v.x; y[4*i+1] = v.y; y[4*i+2] = v.z; y[4*i+3] = v.w;
            }
            if (r0 & 2) {
#pragma unroll
                for (int i = 0; i < 6; i++) resP[i] = CONV11(y, i + 2);
            } else {
#pragma unroll
                for (int i = 0; i < 6; i++) resP[i] = CONV11(y, i);
            }
        }

        float lsum = 0.0f;
#pragma unroll
        for (int i = 0; i < 6; i++) {
            float m1, m2, e11, e22;
            unpk2(resM[i], m1, m2);
            unpk2(resS[i], e11, e22);
            const float m1s = m1 * m1;
            const float m2s = m2 * m2;
            const float m12 = m1 * m2;
            const float s1  = e11 - m1s;
            const float s2  = e22 - m2s;
            const float s12 = resP[i] - m12;
            const float num = (2.0f * m12 + SSIM_C1) * (2.0f * s12 + SSIM_C2);
            const float den = (m1s + m2s + SSIM_C1) * (s1 + s2 + SSIM_C2);
            const float v   = __fdividef(num, den);
            lsum += (i < cnt) ? v : 0.0f;     // select, never mul (NaN-safe)
        }

        // warp reduce -> block reduce -> one global atomic per block
#pragma unroll
        for (int off = 16; off > 0; off >>= 1)
            lsum += __shfl_xor_sync(0xffffffffu, lsum, off);
        if (lane == 0) red[wid] = lsum;
        __syncthreads();
        if (t == 0) {
            float s = 0.0f;
#pragma unroll
            for (int i = 0; i < NWARPS; i++) s += red[i];
            atomicAdd(&g_acc, (double)s);
            __threadfence();
            const unsigned old = atomicAdd(&g_cnt, 1u);
            if (old == NBLOCKS - 1) {
                const ull raw = atomicExch(reinterpret_cast<ull*>(&g_acc), 0ull);
                out[0] = (float)(__longlong_as_double(raw) * (1.0 / 16777216.0));
                g_cnt = 0u;
            }
        }
    }
}

extern "C" void kernel_launch(void* const* d_in, const int* in_sizes, int n_in,
                              void* d_out, int out_size) {
    const float* img1 = (const float*)d_in[0];
    const float* img2 = (const float*)d_in[1];
    float* out = (float*)d_out;

    cudaFuncSetAttribute(ssim_kernel,
                         cudaFuncAttributeMaxDynamicSharedMemorySize, SMEM_BYTES);

    dim3 grid(IMG / TW, IMG / TH, 64);   // 16 x 8 x 64 = 8192 blocks
    ssim_kernel<<<grid, NTHREADS, SMEM_BYTES>>>(img1, img2, out);
}

// round 11
// speedup vs baseline: 1.3741x; 1.3741x over previous
#include <cuda_runtime.h>

// ---------------------------------------------------------------------------
// SSIM fused single-kernel. Tile 32x64 outputs/block, 384 threads, 3 CTAs/SM.
//   P1: stage interleaved AB plane (float2, zero-padded)
//   P2: horizontal 11-tap conv, packed f32x2 scatter -> packed H planes:
//       Hm=(mu1,mu2) float2, Hs=(E11,E22) float2, pp=E12 scalar (transposed)
//   P3: vertical 11-tap conv: 2 packed f32x2 streams + 1 scalar + SSIM + reduce
//       (aligned loads from rb = min(r0 & ~3, 56); residue d in {0,2,4})
// smem = 74,848 B -> 3 CTAs/SM (the R10 regression was smem>limit -> 2 CTAs)
// ---------------------------------------------------------------------------

typedef unsigned long long ull;

#define IMG      512
#define TW       32
#define TH       64
#define HALO     5
#define ROWS     74                // TH + 2*HALO
#define ABROW    46                // AB plane row stride in float2 units
#define ABPLANE  (ROWS * ABROW)    // 3404 float2
#define NTHREADS 384
#define NWARPS   12
#define NBLOCKS  (16 * 8 * 64)     // 8192

#define HPCOL    74                // packed H column stride (float2 units)
#define HPPLANE  (32 * HPCOL)      // 2368 float2 per packed plane
#define PPCOL    76                // pp column stride (floats, mult of 4)

// float offsets
#define HOFF     (2 * ABPLANE)                 // Hm base
#define HSOFF    (HOFF + 2 * HPPLANE)          // Hs base
#define PPOFF    (HSOFF + 2 * HPPLANE)         // pp base
#define SMEM_FLOATS (PPOFF + 32 * PPCOL)
#define SMEM_BYTES  (SMEM_FLOATS * (int)sizeof(float))   // 74,848 B

#define SSIM_C1 0.0001f
#define SSIM_C2 0.0009f

// 1-D Gaussian, sigma=1.5, 11 taps, normalized (literals -> FFMA-imm)
static __device__ __forceinline__ float gwk(int k) {
    const float g[11] = { 1.0283735e-03f, 7.5987582e-03f, 3.6000773e-02f,
                          1.0936068e-01f, 2.1300554e-01f, 2.6601174e-01f,
                          2.1300554e-01f, 1.0936068e-01f, 3.6000773e-02f,
                          7.5987582e-03f, 1.0283735e-03f };
    return g[k];   // k compile-time under full unroll -> immediate
}

#define CONV11(X, c)                                                          \
    fmaf(gwk(0), (X)[(c)+0], fmaf(gwk(1), (X)[(c)+1], fmaf(gwk(2), (X)[(c)+2],\
    fmaf(gwk(3), (X)[(c)+3], fmaf(gwk(4), (X)[(c)+4], fmaf(gwk(5), (X)[(c)+5],\
    fmaf(gwk(6), (X)[(c)+6], fmaf(gwk(7), (X)[(c)+7], fmaf(gwk(8), (X)[(c)+8],\
    fmaf(gwk(9), (X)[(c)+9], gwk(10) * (X)[(c)+10]))))))))))

// packed f32x2 helpers
__device__ __forceinline__ ull pk2(float lo, float hi) {
    ull d; asm("mov.b64 %0, {%1, %2};" : "=l"(d) : "f"(lo), "f"(hi)); return d;
}
__device__ __forceinline__ void unpk2(ull v, float& lo, float& hi) {
    asm("mov.b64 {%0, %1}, %2;" : "=f"(lo), "=f"(hi) : "l"(v));
}
__device__ __forceinline__ ull mul2(ull a, ull b) {
    ull d; asm("mul.rn.f32x2 %0, %1, %2;" : "=l"(d) : "l"(a), "l"(b)); return d;
}
__device__ __forceinline__ ull fma2(ull a, ull b, ull c) {
    ull d; asm("fma.rn.f32x2 %0, %1, %2, %3;" : "=l"(d) : "l"(a), "l"(b), "l"(c)); return d;
}
// packed symmetric 11-tap conv; W[0..5], c compile-time
__device__ __forceinline__ ull conv11p(const ull* y, int c, const ull* W) {
    ull a = mul2(W[0], y[c + 10]);
    a = fma2(W[1], y[c + 9], a);
    a = fma2(W[2], y[c + 8], a);
    a = fma2(W[3], y[c + 7], a);
    a = fma2(W[4], y[c + 6], a);
    a = fma2(W[5], y[c + 5], a);
    a = fma2(W[4], y[c + 4], a);
    a = fma2(W[3], y[c + 3], a);
    a = fma2(W[2], y[c + 2], a);
    a = fma2(W[1], y[c + 1], a);
    a = fma2(W[0], y[c + 0], a);
    return a;
}

static __device__ double   g_acc = 0.0;
static __device__ unsigned g_cnt = 0u;

__global__ __launch_bounds__(NTHREADS, 3)
void ssim_kernel(const float* __restrict__ img1, const float* __restrict__ img2,
                 float* __restrict__ out) {
    extern __shared__ float sm[];
    float2* sAB = reinterpret_cast<float2*>(sm);
    ull*    sHm = reinterpret_cast<ull*>(sm + HOFF);    // packed (mu1,mu2)
    ull*    sHs = reinterpret_cast<ull*>(sm + HSOFF);   // packed (E11,E22)
    float*  sPP = sm + PPOFF;                            // scalar E12
    __shared__ float red[NWARPS];

    const int t    = threadIdx.x;
    const int lane = t & 31;
    const int wid  = t >> 5;        // 0..11
    const int gx0  = blockIdx.x * TW - HALO;
    const int gy0  = blockIdx.y * TH - HALO;
    const float* base1 = img1 + (size_t)blockIdx.z * (IMG * IMG);
    const float* base2 = img2 + (size_t)blockIdx.z * (IMG * IMG);

    // ---- Phase 1: stage interleaved AB (zero-padded), warp per row ----
    for (int r = wid; r < ROWS; r += NWARPS) {
        const int gy = gy0 + r;
        const bool yok = (unsigned)gy < (unsigned)IMG;
        const float* r1 = base1 + gy * IMG;
        const float* r2 = base2 + gy * IMG;
#pragma unroll
        for (int seg = 0; seg < 2; seg++) {
            const int c = lane + seg * 32;
            if (seg == 1 && lane >= 10) break;
            const int gx = gx0 + c;
            const bool ok = yok && (unsigned)gx < (unsigned)IMG;
            sAB[r * ABROW + c] = make_float2(ok ? r1[gx] : 0.0f,
                                             ok ? r2[gx] : 0.0f);
        }
    }
    __syncthreads();

    // ---- Phase 2: horizontal conv, packed scatter, 2 halves of 4 outputs ----
    if (t < 4 * ROWS) {
        const int q = t / ROWS;          // 0..3
        const int r = t - q * ROWS;      // 0..73
        const int cbase = q * 8;
        const float2* abrow = sAB + r * ABROW;

        ull W2[6];
#pragma unroll
        for (int k = 0; k < 6; k++) W2[k] = pk2(gwk(k), gwk(k));

#pragma unroll
        for (int half = 0; half < 2; half++) {
            const int base = cbase + half * 4;   // first output col of half
            ull  mAB[4] = {0ull, 0ull, 0ull, 0ull};
            ull  sSQ[4] = {0ull, 0ull, 0ull, 0ull};
            float pp[4] = {0.f, 0.f, 0.f, 0.f};

            // stream 14 window elements as 7x LDS.128 (2 packed pairs each)
#pragma unroll
            for (int blk = 0; blk < 7; blk++) {
                const ulonglong2 v = *reinterpret_cast<const ulonglong2*>(
                    abrow + base + 2 * blk);
#pragma unroll
                for (int sub = 0; sub < 2; sub++) {
                    const int e = 2 * blk + sub;      // 0..13, compile-time
                    const ull ab = sub ? v.y : v.x;
                    float a, b;
                    unpk2(ab, a, b);
                    const ull   sq   = mul2(ab, ab);
                    const float prod = a * b;
#pragma unroll
                    for (int j = 0; j < 4; j++) {
                        const int k = e - j;          // compile-time
                        if (k >= 0 && k < 11) {
                            const int ks = (k < 6) ? k : 10 - k;
                            mAB[j] = fma2(W2[ks], ab, mAB[j]);
                            sSQ[j] = fma2(W2[ks], sq, sSQ[j]);
                            pp[j]  = fmaf(gwk(k), prod, pp[j]);
                        }
                    }
                }
            }

            // packed stores into transposed H planes
#pragma unroll
            for (int j = 0; j < 4; j++) {
                const int hc = base + j;
                sHm[hc * HPCOL + r] = mAB[j];   // ST.64, conflict-free
                sHs[hc * HPCOL + r] = sSQ[j];
                sPP[hc * PPCOL + r] = pp[j];
            }
        }
    }
    __syncthreads();

    // ---- Phase 3: vertical conv (packed x2 + scalar) + SSIM + reduce ----
    {
        // warps 0..7: 6 rows from r0=6w ; warps 8..11: 4 rows from 48+4(w-8)
        const int six = (wid < 8);
        const int r0  = six ? 6 * wid : 48 + 4 * (wid - 8);
        const int cnt = six ? 6 : 4;
        int rb = r0 & ~3;
        if (rb > 56) rb = 56;           // cap: window rows stay <= 73
        const int d = r0 - rb;          // residue in {0,2,4}; d==4 only wid 11
        const int col = lane;

        ull W2[6];
#pragma unroll
        for (int k = 0; k < 6; k++) W2[k] = pk2(gwk(k), gwk(k));

        ull resM[6], resS[6];
        {
            ull y[18];
            const ulonglong2* p = reinterpret_cast<const ulonglong2*>(
                sHm + col * HPCOL + rb);
#pragma unroll
            for (int i = 0; i < 9; i++) {
                const ulonglong2 v = p[i];
                y[2 * i]     = v.x;
                y[2 * i + 1] = v.y;
            }
            if (d == 0) {
#pragma unroll
                for (int i = 0; i < 6; i++) resM[i] = conv11p(y, i, W2);
            } else if (d == 2) {
#pragma unroll
                for (int i = 0; i < 6; i++) resM[i] = conv11p(y, i + 2, W2);
            } else {                    // d == 4: only 4 valid outputs
#pragma unroll
                for (int i = 0; i < 4; i++) resM[i] = conv11p(y, i + 4, W2);
                resM[4] = resM[5] = 0ull;
            }
        }
        {
            ull y[18];
            const ulonglong2* p = reinterpret_cast<const ulonglong2*>(
                sHs + col * HPCOL + rb);
#pragma unroll
            for (int i = 0; i < 9; i++) {
                const ulonglong2 v = p[i];
                y[2 * i]     = v.x;
                y[2 * i + 1] = v.y;
            }
            if (d == 0) {
#pragma unroll
                for (int i = 0; i < 6; i++) resS[i] = conv11p(y, i, W2);
            } else if (d == 2) {
#pragma unroll
                for (int i = 0; i < 6; i++) resS[i] = conv11p(y, i + 2, W2);
            } else {
#pragma unroll
                for (int i = 0; i < 4; i++) resS[i] = conv11p(y, i + 4, W2);
                resS[4] = resS[5] = 0ull;
            }
        }
        float resP[6];
        {
            float y[20];
            const float* p = sPP + col * PPCOL + rb;   // rows rb..rb+19 <= 75
#pragma unroll
            for (int i = 0; i < 5; i++) {
                const float4 v = *reinterpret_cast<const float4*>(p + 4 * i);
                y[4*i+0] = v.x; y[4*i+1] = v.y; y[4*i+2] = v.z; y[4*i+3] = v.w;
            }
            if (d == 0) {
#pragma unroll
                for (int i = 0; i < 6; i++) resP[i] = CONV11(y, i);
            } else if (d == 2) {
#pragma unroll
                for (int i = 0; i < 6; i++) resP[i] = CONV11(y, i + 2);
            } else {
#pragma unroll
                for (int i = 0; i < 4; i++) resP[i] = CONV11(y, i + 4);
                resP[4] = resP[5] = 0.0f;
            }
        }

        float lsum = 0.0f;
#pragma unroll
        for (int i = 0; i < 6; i++) {
            float m1, m2, e11, e22;
            unpk2(resM[i], m1, m2);
            unpk2(resS[i], e11, e22);
            const float m1s = m1 * m1;
            const float m2s = m2 * m2;
            const float m12 = m1 * m2;
            const float s1  = e11 - m1s;
            const float s2  = e22 - m2s;
            const float s12 = resP[i] - m12;
            const float num = (2.0f * m12 + SSIM_C1) * (2.0f * s12 + SSIM_C2);
            const float den = (m1s + m2s + SSIM_C1) * (s1 + s2 + SSIM_C2);
            const float v   = __fdividef(num, den);
            lsum += (i < cnt) ? v : 0.0f;     // select, never mul (NaN-safe)
        }

        // warp reduce -> block reduce -> one global atomic per block
#pragma unroll
        for (int off = 16; off > 0; off >>= 1)
            lsum += __shfl_xor_sync(0xffffffffu, lsum, off);
        if (lane == 0) red[wid] = lsum;
        __syncthreads();
        if (t == 0) {
            float s = 0.0f;
#pragma unroll
            for (int i = 0; i < NWARPS; i++) s += red[i];
            atomicAdd(&g_acc, (double)s);
            __threadfence();
            const unsigned old = atomicAdd(&g_cnt, 1u);
            if (old == NBLOCKS - 1) {
                const ull raw = atomicExch(reinterpret_cast<ull*>(&g_acc), 0ull);
                out[0] = (float)(__longlong_as_double(raw) * (1.0 / 16777216.0));
                g_cnt = 0u;
            }
        }
    }
}

extern "C" void kernel_launch(void* const* d_in, const int* in_sizes, int n_in,
                              void* d_out, int out_size) {
    const float* img1 = (const float*)d_in[0];
    const float* img2 = (const float*)d_in[1];
    float* out = (float*)d_out;

    cudaFuncSetAttribute(ssim_kernel,
                         cudaFuncAttributeMaxDynamicSharedMemorySize, SMEM_BYTES);

    dim3 grid(IMG / TW, IMG / TH, 64);   // 16 x 8 x 64 = 8192 blocks
    ssim_kernel<<<grid, NTHREADS, SMEM_BYTES>>>(img1, img2, out);
}